// round 7
// baseline (speedup 1.0000x reference)
#include <cuda_runtime.h>
#include <cuda_fp16.h>
#include <cstdint>

#define NN 50000
#define EE 800000
#define SCAN_T 2048

// ---------------- scratch (__device__ globals; allocation-free) ----------------
__device__ __half g_ha[NN * 128];      // activations fp16, ping
__device__ __half g_hb[NN * 128];      // activations fp16, pong
__device__ float  g_nsrc[NN];
__device__ float  g_ndst[NN];
__device__ int    g_dego[NN];
__device__ int    g_degi[NN];
__device__ int    g_off[NN + 1];
__device__ int    g_cur[NN];
__device__ int    g_csr[EE];
__device__ int    g_tsum[SCAN_T];

// ---------------- f32x2 packed helpers (Blackwell) ----------------
__device__ __forceinline__ unsigned long long pack2(float a, float b) {
    unsigned long long r;
    asm("mov.b64 %0, {%1, %2};" : "=l"(r) : "f"(a), "f"(b));
    return r;
}
__device__ __forceinline__ void unpack2(unsigned long long v, float& a, float& b) {
    asm("mov.b64 {%0, %1}, %2;" : "=f"(a), "=f"(b) : "l"(v));
}
__device__ __forceinline__ void addx2(unsigned long long& acc, unsigned long long v) {
    asm("add.rn.f32x2 %0, %0, %1;" : "+l"(acc) : "l"(v));
}
__device__ __forceinline__ void mulx2(unsigned long long& acc, unsigned long long v) {
    asm("mul.rn.f32x2 %0, %0, %1;" : "+l"(acc) : "l"(v));
}

// ---------------- CSR build ----------------
__global__ void zero_deg_kernel(int* a, int* b, int n) {
    int i = blockIdx.x * blockDim.x + threadIdx.x;
    if (i < n) { a[i] = 0; b[i] = 0; }
}

__global__ void degree_kernel(const int* __restrict__ src, const int* __restrict__ dst,
                              int* dego, int* degi, int E) {
    int i = blockIdx.x * blockDim.x + threadIdx.x;
    int E4 = E >> 2;
    if (i < E4) {
        int4 s = __ldg((const int4*)src + i);
        int4 d = __ldg((const int4*)dst + i);
        atomicAdd(&dego[s.x], 1);
        atomicAdd(&dego[s.y], 1);
        atomicAdd(&dego[s.z], 1);
        atomicAdd(&dego[s.w], 1);
        atomicAdd(&degi[d.x], 1);
        atomicAdd(&degi[d.y], 1);
        atomicAdd(&degi[d.z], 1);
        atomicAdd(&degi[d.w], 1);
    }
    if (i == 0) {
        for (int e = E4 << 2; e < E; e++) {
            atomicAdd(&dego[src[e]], 1);
            atomicAdd(&degi[dst[e]], 1);
        }
    }
}

__global__ void partsum_kernel(const int* __restrict__ degi, int* tsum, int N) {
    int t = blockIdx.x * blockDim.x + threadIdx.x;
    if (t >= SCAN_T) return;
    int chunk = (N + SCAN_T - 1) / SCAN_T;
    int b = t * chunk, e = min(b + chunk, N);
    int s = 0;
    for (int i = b; i < e; i++) s += degi[i];
    tsum[t] = s;
}

__global__ void scanpart_kernel(int* tsum) {
    __shared__ int sm[1024];
    int t = threadIdx.x;
    int a = tsum[2 * t], b = tsum[2 * t + 1];
    sm[t] = a + b;
    __syncthreads();
    for (int d = 1; d < 1024; d <<= 1) {
        int v = (t >= d) ? sm[t - d] : 0;
        __syncthreads();
        sm[t] += v;
        __syncthreads();
    }
    int excl = (t > 0) ? sm[t - 1] : 0;
    tsum[2 * t] = excl;
    tsum[2 * t + 1] = excl + a;
}

__global__ void writeoff_kernel(const int* __restrict__ degi, const int* __restrict__ dego,
                                const int* __restrict__ tsum,
                                int* off, int* cur, float* nsrc, float* ndst, int N) {
    int t = blockIdx.x * blockDim.x + threadIdx.x;
    if (t >= SCAN_T) return;
    int chunk = (N + SCAN_T - 1) / SCAN_T;
    int b = t * chunk, e = min(b + chunk, N);
    int run = tsum[t];
    for (int i = b; i < e; i++) {
        off[i] = run;
        cur[i] = run;
        int di = degi[i];
        run += di;
        ndst[i] = rsqrtf((float)max(di, 1));
        nsrc[i] = rsqrtf((float)max(dego[i], 1));
    }
    if (t == SCAN_T - 1) off[N] = run;
}

__global__ void fill_kernel(const int* __restrict__ src, const int* __restrict__ dst,
                            int* cur, int* csr, int E) {
    int i = blockIdx.x * blockDim.x + threadIdx.x;
    int E4 = E >> 2;
    if (i < E4) {
        int4 s = __ldg((const int4*)src + i);
        int4 d = __ldg((const int4*)dst + i);
        int p0 = atomicAdd(&cur[d.x], 1);
        int p1 = atomicAdd(&cur[d.y], 1);
        int p2 = atomicAdd(&cur[d.z], 1);
        int p3 = atomicAdd(&cur[d.w], 1);
        csr[p0] = s.x;
        csr[p1] = s.y;
        csr[p2] = s.z;
        csr[p3] = s.w;
    }
    if (i == 0) {
        for (int e = E4 << 2; e < E; e++) {
            int p = atomicAdd(&cur[dst[e]], 1);
            csr[p] = src[e];
        }
    }
}

// ---------------- proj GEMM (K=64): h = fp16(relu(x @ Wp + bp) * nsrc) ----------------
__global__ void gemm64_kernel(const float* __restrict__ X, const float* __restrict__ W,
                              const float* __restrict__ B,
                              const float* __restrict__ postscale,
                              __half* __restrict__ out, int n) {
    extern __shared__ float sm[];
    float* w_sh = sm;              // 64 * 128
    float* x_sh = sm + 64 * 128;   // 64 * 64

    const int tx = threadIdx.x;
    const int row0 = blockIdx.x * 64;

    {
        const float4* W4 = (const float4*)W;
        float4* w4 = (float4*)w_sh;
        #pragma unroll
        for (int i = tx; i < 64 * 32; i += 256) w4[i] = W4[i];
    }
    {
        const float4* X4 = (const float4*)X;
        float4* x4 = (float4*)x_sh;
        #pragma unroll
        for (int i = tx; i < 64 * 16; i += 256) {
            int r = i >> 4;
            int c = i & 15;
            int gr = row0 + r;
            if (gr >= n) gr = n - 1;
            x4[i] = X4[(long)gr * 16 + c];
        }
    }
    __syncthreads();

    const int cg = tx & 31;
    const int rbase = (tx >> 5) * 8;

    float acc[8][4];
    #pragma unroll
    for (int i = 0; i < 8; i++)
        #pragma unroll
        for (int j = 0; j < 4; j++) acc[i][j] = 0.0f;

    #pragma unroll 2
    for (int k = 0; k < 64; k += 4) {
        float4 wv[4];
        #pragma unroll
        for (int t = 0; t < 4; t++)
            wv[t] = *(const float4*)&w_sh[(k + t) * 128 + cg * 4];
        #pragma unroll
        for (int i = 0; i < 8; i++) {
            float4 xv = *(const float4*)&x_sh[(rbase + i) * 64 + k];
            acc[i][0] = fmaf(xv.x, wv[0].x, acc[i][0]);
            acc[i][1] = fmaf(xv.x, wv[0].y, acc[i][1]);
            acc[i][2] = fmaf(xv.x, wv[0].z, acc[i][2]);
            acc[i][3] = fmaf(xv.x, wv[0].w, acc[i][3]);
            acc[i][0] = fmaf(xv.y, wv[1].x, acc[i][0]);
            acc[i][1] = fmaf(xv.y, wv[1].y, acc[i][1]);
            acc[i][2] = fmaf(xv.y, wv[1].z, acc[i][2]);
            acc[i][3] = fmaf(xv.y, wv[1].w, acc[i][3]);
            acc[i][0] = fmaf(xv.z, wv[2].x, acc[i][0]);
            acc[i][1] = fmaf(xv.z, wv[2].y, acc[i][1]);
            acc[i][2] = fmaf(xv.z, wv[2].z, acc[i][2]);
            acc[i][3] = fmaf(xv.z, wv[2].w, acc[i][3]);
            acc[i][0] = fmaf(xv.w, wv[3].x, acc[i][0]);
            acc[i][1] = fmaf(xv.w, wv[3].y, acc[i][1]);
            acc[i][2] = fmaf(xv.w, wv[3].z, acc[i][2]);
            acc[i][3] = fmaf(xv.w, wv[3].w, acc[i][3]);
        }
    }

    float4 bv = ((const float4*)B)[cg];
    #pragma unroll
    for (int i = 0; i < 8; i++) {
        int r = row0 + rbase + i;
        if (r < n) {
            float sc = __ldg(&postscale[r]);
            float ox = fmaxf(acc[i][0] + bv.x, 0.0f) * sc;
            float oy = fmaxf(acc[i][1] + bv.y, 0.0f) * sc;
            float oz = fmaxf(acc[i][2] + bv.z, 0.0f) * sc;
            float ow = fmaxf(acc[i][3] + bv.w, 0.0f) * sc;
            __half2 p0 = __floats2half2_rn(ox, oy);
            __half2 p1 = __floats2half2_rn(oz, ow);
            uint2 st;
            st.x = *(uint32_t*)&p0;
            st.y = *(uint32_t*)&p1;
            *(uint2*)(out + (long)r * 128 + cg * 4) = st;
        }
    }
}

// ---------------- fused layer: gather(h_in fp16 via CSR) -> smem -> GEMM -> relu ----------------
// h_in and outv are DISTINCT buffers (ping-pong) — no intra-grid RAW hazard.
template <bool HALF_OUT>
__global__ void __launch_bounds__(256, 2)
fused_layer_kernel(const int* __restrict__ off, const int* __restrict__ csr,
                   const float* __restrict__ ndst,
                   const uint2* __restrict__ h2,
                   const float* __restrict__ W, const float* __restrict__ B,
                   const float* __restrict__ postscale,
                   void* __restrict__ outv, int n) {
    extern __shared__ float sm[];
    float* w_sh = sm;               // 128 * 128
    float* x_sh = sm + 128 * 128;   // 64 * 128

    const int tx = threadIdx.x;
    const int wid = tx >> 5;
    const int lane = tx & 31;
    const int row0 = blockIdx.x * 64;

    // ---- W load (independent LDGs in flight alongside gather)
    {
        const float4* W4 = (const float4*)W;
        float4* w4 = (float4*)w_sh;
        #pragma unroll
        for (int i = tx; i < 128 * 32; i += 256) w4[i] = W4[i];
    }

    // ---- gather phase: warp handles 8 nodes; lane covers 4 cols (uint2 of fp16)
    #pragma unroll 1
    for (int r = 0; r < 8; r++) {
        int node = row0 + wid * 8 + r;
        float4 o = make_float4(0.f, 0.f, 0.f, 0.f);
        if (node < n) {
            int beg = __ldg(&off[node]);
            int end = __ldg(&off[node + 1]);
            unsigned long long a0 = pack2(0.f, 0.f), a1 = a0;
            int j = beg;
            for (; j + 4 <= end; j += 4) {
                int s0 = __ldg(&csr[j]);
                int s1 = __ldg(&csr[j + 1]);
                int s2 = __ldg(&csr[j + 2]);
                int s3 = __ldg(&csr[j + 3]);
                uint2 v0 = __ldg(&h2[(long)s0 * 32 + lane]);
                uint2 v1 = __ldg(&h2[(long)s1 * 32 + lane]);
                uint2 v2 = __ldg(&h2[(long)s2 * 32 + lane]);
                uint2 v3 = __ldg(&h2[(long)s3 * 32 + lane]);
                float2 f;
                f = __half22float2(*(const __half2*)&v0.x); addx2(a0, pack2(f.x, f.y));
                f = __half22float2(*(const __half2*)&v0.y); addx2(a1, pack2(f.x, f.y));
                f = __half22float2(*(const __half2*)&v1.x); addx2(a0, pack2(f.x, f.y));
                f = __half22float2(*(const __half2*)&v1.y); addx2(a1, pack2(f.x, f.y));
                f = __half22float2(*(const __half2*)&v2.x); addx2(a0, pack2(f.x, f.y));
                f = __half22float2(*(const __half2*)&v2.y); addx2(a1, pack2(f.x, f.y));
                f = __half22float2(*(const __half2*)&v3.x); addx2(a0, pack2(f.x, f.y));
                f = __half22float2(*(const __half2*)&v3.y); addx2(a1, pack2(f.x, f.y));
            }
            for (; j < end; j++) {
                int s = __ldg(&csr[j]);
                uint2 v = __ldg(&h2[(long)s * 32 + lane]);
                float2 f;
                f = __half22float2(*(const __half2*)&v.x); addx2(a0, pack2(f.x, f.y));
                f = __half22float2(*(const __half2*)&v.y); addx2(a1, pack2(f.x, f.y));
            }
            float nd = __ldg(&ndst[node]);
            unsigned long long nn = pack2(nd, nd);
            mulx2(a0, nn);
            mulx2(a1, nn);
            unpack2(a0, o.x, o.y);
            unpack2(a1, o.z, o.w);
        }
        *(float4*)&x_sh[(wid * 8 + r) * 128 + lane * 4] = o;
    }
    __syncthreads();

    // ---- GEMM phase: thread tile 8 rows x 4 cols, k-chunk 4
    const int cg = tx & 31;
    const int rbase = (tx >> 5) * 8;

    float acc[8][4];
    #pragma unroll
    for (int i = 0; i < 8; i++)
        #pragma unroll
        for (int j = 0; j < 4; j++) acc[i][j] = 0.0f;

    #pragma unroll 2
    for (int k = 0; k < 128; k += 4) {
        float4 wv[4];
        #pragma unroll
        for (int t = 0; t < 4; t++)
            wv[t] = *(const float4*)&w_sh[(k + t) * 128 + cg * 4];
        #pragma unroll
        for (int i = 0; i < 8; i++) {
            float4 xv = *(const float4*)&x_sh[(rbase + i) * 128 + k];
            acc[i][0] = fmaf(xv.x, wv[0].x, acc[i][0]);
            acc[i][1] = fmaf(xv.x, wv[0].y, acc[i][1]);
            acc[i][2] = fmaf(xv.x, wv[0].z, acc[i][2]);
            acc[i][3] = fmaf(xv.x, wv[0].w, acc[i][3]);
            acc[i][0] = fmaf(xv.y, wv[1].x, acc[i][0]);
            acc[i][1] = fmaf(xv.y, wv[1].y, acc[i][1]);
            acc[i][2] = fmaf(xv.y, wv[1].z, acc[i][2]);
            acc[i][3] = fmaf(xv.y, wv[1].w, acc[i][3]);
            acc[i][0] = fmaf(xv.z, wv[2].x, acc[i][0]);
            acc[i][1] = fmaf(xv.z, wv[2].y, acc[i][1]);
            acc[i][2] = fmaf(xv.z, wv[2].z, acc[i][2]);
            acc[i][3] = fmaf(xv.z, wv[2].w, acc[i][3]);
            acc[i][0] = fmaf(xv.w, wv[3].x, acc[i][0]);
            acc[i][1] = fmaf(xv.w, wv[3].y, acc[i][1]);
            acc[i][2] = fmaf(xv.w, wv[3].z, acc[i][2]);
            acc[i][3] = fmaf(xv.w, wv[3].w, acc[i][3]);
        }
    }

    float4 bv = ((const float4*)B)[cg];
    #pragma unroll
    for (int i = 0; i < 8; i++) {
        int r = row0 + rbase + i;
        if (r < n) {
            float sc = postscale ? __ldg(&postscale[r]) : 1.0f;
            float ox = fmaxf(acc[i][0] + bv.x, 0.0f) * sc;
            float oy = fmaxf(acc[i][1] + bv.y, 0.0f) * sc;
            float oz = fmaxf(acc[i][2] + bv.z, 0.0f) * sc;
            float ow = fmaxf(acc[i][3] + bv.w, 0.0f) * sc;
            if (HALF_OUT) {
                __half2 p0 = __floats2half2_rn(ox, oy);
                __half2 p1 = __floats2half2_rn(oz, ow);
                uint2 st;
                st.x = *(uint32_t*)&p0;
                st.y = *(uint32_t*)&p1;
                *(uint2*)((__half*)outv + (long)r * 128 + cg * 4) = st;
            } else {
                float4 o = make_float4(ox, oy, oz, ow);
                *(float4*)((float*)outv + (long)r * 128 + cg * 4) = o;
            }
        }
    }
}

extern "C" void kernel_launch(void* const* d_in, const int* in_sizes, int n_in,
                              void* d_out, int out_size) {
    const float* x_raw = (const float*)d_in[0];
    const int*   src   = (const int*)d_in[1];
    const int*   dst   = (const int*)d_in[2];
    const float* Wp    = (const float*)d_in[3];
    const float* bp    = (const float*)d_in[4];
    const float* Wl    = (const float*)d_in[5];
    const float* bl    = (const float*)d_in[6];
    float* out = (float*)d_out;

    const int N = in_sizes[0] / 64;
    const int E = in_sizes[1];

    __half *ha, *hb;
    float *nsrc, *ndst;
    int *dego, *degi, *off, *cur, *csr, *tsum;
    cudaGetSymbolAddress((void**)&ha, g_ha);
    cudaGetSymbolAddress((void**)&hb, g_hb);
    cudaGetSymbolAddress((void**)&nsrc, g_nsrc);
    cudaGetSymbolAddress((void**)&ndst, g_ndst);
    cudaGetSymbolAddress((void**)&dego, g_dego);
    cudaGetSymbolAddress((void**)&degi, g_degi);
    cudaGetSymbolAddress((void**)&off, g_off);
    cudaGetSymbolAddress((void**)&cur, g_cur);
    cudaGetSymbolAddress((void**)&csr, g_csr);
    cudaGetSymbolAddress((void**)&tsum, g_tsum);

    const int FUSED_SMEM = (128 * 128 + 64 * 128) * (int)sizeof(float);   // 96KB
    const int PROJ_SMEM = (64 * 128 + 64 * 64) * (int)sizeof(float);
    cudaFuncSetAttribute((const void*)fused_layer_kernel<true>,
                         cudaFuncAttributeMaxDynamicSharedMemorySize, FUSED_SMEM);
    cudaFuncSetAttribute((const void*)fused_layer_kernel<false>,
                         cudaFuncAttributeMaxDynamicSharedMemorySize, FUSED_SMEM);
    cudaFuncSetAttribute((const void*)gemm64_kernel,
                         cudaFuncAttributeMaxDynamicSharedMemorySize, PROJ_SMEM);

    // 1) degrees -> norms + CSR(by dst)
    const int E4 = E >> 2;
    zero_deg_kernel<<<(N + 255) / 256, 256>>>(dego, degi, N);
    degree_kernel<<<(E4 + 255) / 256, 256>>>(src, dst, dego, degi, E);
    partsum_kernel<<<SCAN_T / 256, 256>>>(degi, tsum, N);
    scanpart_kernel<<<1, 1024>>>(tsum);
    writeoff_kernel<<<SCAN_T / 256, 256>>>(degi, dego, tsum, off, cur, nsrc, ndst, N);
    fill_kernel<<<(E4 + 255) / 256, 256>>>(src, dst, cur, csr, E);

    // 2) ha = fp16( relu(x_raw @ Wp + bp) * norm_src )
    gemm64_kernel<<<(N + 63) / 64, 256, PROJ_SMEM>>>(x_raw, Wp, bp, nsrc, ha, N);

    // 3) fused layers with ping-pong buffers: l0 ha->hb, l1 hb->ha, l2 ha->out
    const int gblocks = (N + 63) / 64;
    fused_layer_kernel<true><<<gblocks, 256, FUSED_SMEM>>>(
        off, csr, ndst, (const uint2*)ha, Wl, bl, nsrc, hb, N);
    fused_layer_kernel<true><<<gblocks, 256, FUSED_SMEM>>>(
        off, csr, ndst, (const uint2*)hb, Wl + 16384, bl + 128, nsrc, ha, N);
    fused_layer_kernel<false><<<gblocks, 256, FUSED_SMEM>>>(
        off, csr, ndst, (const uint2*)ha, Wl + 2 * 16384, bl + 2 * 128, nullptr, out, N);
}

// round 8
// speedup vs baseline: 1.3072x; 1.3072x over previous
#include <cuda_runtime.h>
#include <cuda_fp16.h>
#include <cstdint>

#define NN 50000
#define EE 800000
#define SCAN_T 2048

// ---------------- scratch (__device__ globals; allocation-free) ----------------
__device__ __half g_h[NN * 128];       // activations fp16 (gather-side)
__device__ __half g_agg[NN * 128];     // SpMM result fp16 (GEMM input)
__device__ float  g_nsrc[NN];
__device__ float  g_ndst[NN];
__device__ int    g_dego[NN];
__device__ int    g_degi[NN];
__device__ int    g_off[NN + 1];
__device__ int    g_cur[NN];
__device__ int    g_csr[EE];
__device__ int    g_tsum[SCAN_T];

// ---------------- f32x2 packed helpers (Blackwell) ----------------
__device__ __forceinline__ unsigned long long pack2(float a, float b) {
    unsigned long long r;
    asm("mov.b64 %0, {%1, %2};" : "=l"(r) : "f"(a), "f"(b));
    return r;
}
__device__ __forceinline__ void unpack2(unsigned long long v, float& a, float& b) {
    asm("mov.b64 {%0, %1}, %2;" : "=f"(a), "=f"(b) : "l"(v));
}
__device__ __forceinline__ void addx2(unsigned long long& acc, unsigned long long v) {
    asm("add.rn.f32x2 %0, %0, %1;" : "+l"(acc) : "l"(v));
}
__device__ __forceinline__ void mulx2(unsigned long long& acc, unsigned long long v) {
    asm("mul.rn.f32x2 %0, %0, %1;" : "+l"(acc) : "l"(v));
}
__device__ __forceinline__ void acc_h2(unsigned long long& a0, unsigned long long& a1,
                                       uint2 v) {
    float2 f;
    f = __half22float2(*(const __half2*)&v.x);
    addx2(a0, pack2(f.x, f.y));
    f = __half22float2(*(const __half2*)&v.y);
    addx2(a1, pack2(f.x, f.y));
}

// ---------------- CSR build ----------------
__global__ void zero_deg_kernel(int* a, int* b, int n) {
    int i = blockIdx.x * blockDim.x + threadIdx.x;
    if (i < n) { a[i] = 0; b[i] = 0; }
}

__global__ void degree_kernel(const int* __restrict__ src, const int* __restrict__ dst,
                              int* dego, int* degi, int E) {
    int i = blockIdx.x * blockDim.x + threadIdx.x;
    int E4 = E >> 2;
    if (i < E4) {
        int4 s = __ldg((const int4*)src + i);
        int4 d = __ldg((const int4*)dst + i);
        atomicAdd(&dego[s.x], 1);
        atomicAdd(&dego[s.y], 1);
        atomicAdd(&dego[s.z], 1);
        atomicAdd(&dego[s.w], 1);
        atomicAdd(&degi[d.x], 1);
        atomicAdd(&degi[d.y], 1);
        atomicAdd(&degi[d.z], 1);
        atomicAdd(&degi[d.w], 1);
    }
    if (i == 0) {
        for (int e = E4 << 2; e < E; e++) {
            atomicAdd(&dego[src[e]], 1);
            atomicAdd(&degi[dst[e]], 1);
        }
    }
}

__global__ void partsum_kernel(const int* __restrict__ degi, int* tsum, int N) {
    int t = blockIdx.x * blockDim.x + threadIdx.x;
    if (t >= SCAN_T) return;
    int chunk = (N + SCAN_T - 1) / SCAN_T;
    int b = t * chunk, e = min(b + chunk, N);
    int s = 0;
    for (int i = b; i < e; i++) s += degi[i];
    tsum[t] = s;
}

__global__ void scanpart_kernel(int* tsum) {
    __shared__ int sm[1024];
    int t = threadIdx.x;
    int a = tsum[2 * t], b = tsum[2 * t + 1];
    sm[t] = a + b;
    __syncthreads();
    for (int d = 1; d < 1024; d <<= 1) {
        int v = (t >= d) ? sm[t - d] : 0;
        __syncthreads();
        sm[t] += v;
        __syncthreads();
    }
    int excl = (t > 0) ? sm[t - 1] : 0;
    tsum[2 * t] = excl;
    tsum[2 * t + 1] = excl + a;
}

__global__ void writeoff_kernel(const int* __restrict__ degi, const int* __restrict__ dego,
                                const int* __restrict__ tsum,
                                int* off, int* cur, float* nsrc, float* ndst, int N) {
    int t = blockIdx.x * blockDim.x + threadIdx.x;
    if (t >= SCAN_T) return;
    int chunk = (N + SCAN_T - 1) / SCAN_T;
    int b = t * chunk, e = min(b + chunk, N);
    int run = tsum[t];
    for (int i = b; i < e; i++) {
        off[i] = run;
        cur[i] = run;
        int di = degi[i];
        run += di;
        ndst[i] = rsqrtf((float)max(di, 1));
        nsrc[i] = rsqrtf((float)max(dego[i], 1));
    }
    if (t == SCAN_T - 1) off[N] = run;
}

__global__ void fill_kernel(const int* __restrict__ src, const int* __restrict__ dst,
                            int* cur, int* csr, int E) {
    int i = blockIdx.x * blockDim.x + threadIdx.x;
    int E4 = E >> 2;
    if (i < E4) {
        int4 s = __ldg((const int4*)src + i);
        int4 d = __ldg((const int4*)dst + i);
        int p0 = atomicAdd(&cur[d.x], 1);
        int p1 = atomicAdd(&cur[d.y], 1);
        int p2 = atomicAdd(&cur[d.z], 1);
        int p3 = atomicAdd(&cur[d.w], 1);
        csr[p0] = s.x;
        csr[p1] = s.y;
        csr[p2] = s.z;
        csr[p3] = s.w;
    }
    if (i == 0) {
        for (int e = E4 << 2; e < E; e++) {
            int p = atomicAdd(&cur[dst[e]], 1);
            csr[p] = src[e];
        }
    }
}

// ---------------- pull SpMM: agg[d] = fp16( ndst[d] * sum_{s in in(d)} h[s] ) ----------------
// One warp per dst node; lane owns 4 cols (uint2 fp16). 8-edge unrolled (MLP 8).
__global__ void pull_kernel(const int* __restrict__ off, const int* __restrict__ csr,
                            const float* __restrict__ ndst,
                            const uint2* __restrict__ h2, uint2* __restrict__ agg2, int N) {
    int w = (blockIdx.x * blockDim.x + threadIdx.x) >> 5;
    int lane = threadIdx.x & 31;
    if (w >= N) return;
    int beg = __ldg(&off[w]);
    int end = __ldg(&off[w + 1]);

    unsigned long long a0 = pack2(0.f, 0.f), a1 = a0;

    int j = beg;
    for (; j + 8 <= end; j += 8) {
        int s0 = __ldg(&csr[j]);
        int s1 = __ldg(&csr[j + 1]);
        int s2 = __ldg(&csr[j + 2]);
        int s3 = __ldg(&csr[j + 3]);
        int s4 = __ldg(&csr[j + 4]);
        int s5 = __ldg(&csr[j + 5]);
        int s6 = __ldg(&csr[j + 6]);
        int s7 = __ldg(&csr[j + 7]);
        uint2 v0 = __ldg(&h2[(long)s0 * 32 + lane]);
        uint2 v1 = __ldg(&h2[(long)s1 * 32 + lane]);
        uint2 v2 = __ldg(&h2[(long)s2 * 32 + lane]);
        uint2 v3 = __ldg(&h2[(long)s3 * 32 + lane]);
        uint2 v4 = __ldg(&h2[(long)s4 * 32 + lane]);
        uint2 v5 = __ldg(&h2[(long)s5 * 32 + lane]);
        uint2 v6 = __ldg(&h2[(long)s6 * 32 + lane]);
        uint2 v7 = __ldg(&h2[(long)s7 * 32 + lane]);
        acc_h2(a0, a1, v0);
        acc_h2(a0, a1, v1);
        acc_h2(a0, a1, v2);
        acc_h2(a0, a1, v3);
        acc_h2(a0, a1, v4);
        acc_h2(a0, a1, v5);
        acc_h2(a0, a1, v6);
        acc_h2(a0, a1, v7);
    }
    for (; j < end; j++) {
        int s = __ldg(&csr[j]);
        acc_h2(a0, a1, __ldg(&h2[(long)s * 32 + lane]));
    }

    float nd = __ldg(&ndst[w]);
    unsigned long long nn = pack2(nd, nd);
    mulx2(a0, nn);
    mulx2(a1, nn);
    float4 o;
    unpack2(a0, o.x, o.y);
    unpack2(a1, o.z, o.w);
    __half2 p0 = __floats2half2_rn(o.x, o.y);
    __half2 p1 = __floats2half2_rn(o.z, o.w);
    uint2 st;
    st.x = *(uint32_t*)&p0;
    st.y = *(uint32_t*)&p1;
    agg2[(long)w * 32 + lane] = st;
}

// ---------------- GEMM (X fp16, W fp32) + bias + relu + optional row post-scale ----------------
// HALF_OUT: writes fp16 h (gather-side); else fp32 final out.
// Block: 256 threads, 64 rows x 128 cols. Thread tile: 8 rows x 4 cols, k-chunk 4.
template <bool HALF_OUT>
__global__ void gemm128_kernel(const uint2* __restrict__ X2, const float* __restrict__ W,
                               const float* __restrict__ B,
                               const float* __restrict__ postscale,
                               void* __restrict__ outv, int n) {
    extern __shared__ float sm[];
    float* w_sh = sm;               // 128 * 128
    float* x_sh = sm + 128 * 128;   // 64 * 128

    const int tx = threadIdx.x;
    const int row0 = blockIdx.x * 64;

    {
        const float4* W4 = (const float4*)W;
        float4* w4 = (float4*)w_sh;
        #pragma unroll
        for (int i = tx; i < 128 * 32; i += 256) w4[i] = W4[i];
    }
    {
        // X: 64 rows x 32 uint2 (fp16x4 per uint2); convert to fp32 in smem
        #pragma unroll
        for (int i = tx; i < 64 * 32; i += 256) {
            int r = i >> 5;
            int c = i & 31;
            int gr = row0 + r;
            if (gr >= n) gr = n - 1;
            uint2 v = __ldg(X2 + (long)gr * 32 + c);
            float2 f0 = __half22float2(*(const __half2*)&v.x);
            float2 f1 = __half22float2(*(const __half2*)&v.y);
            *(float4*)&x_sh[r * 128 + c * 4] = make_float4(f0.x, f0.y, f1.x, f1.y);
        }
    }
    __syncthreads();

    const int cg = tx & 31;
    const int rbase = (tx >> 5) * 8;

    float acc[8][4];
    #pragma unroll
    for (int i = 0; i < 8; i++)
        #pragma unroll
        for (int j = 0; j < 4; j++) acc[i][j] = 0.0f;

    #pragma unroll 2
    for (int k = 0; k < 128; k += 4) {
        float4 wv[4];
        #pragma unroll
        for (int t = 0; t < 4; t++)
            wv[t] = *(const float4*)&w_sh[(k + t) * 128 + cg * 4];
        #pragma unroll
        for (int i = 0; i < 8; i++) {
            float4 xv = *(const float4*)&x_sh[(rbase + i) * 128 + k];
            acc[i][0] = fmaf(xv.x, wv[0].x, acc[i][0]);
            acc[i][1] = fmaf(xv.x, wv[0].y, acc[i][1]);
            acc[i][2] = fmaf(xv.x, wv[0].z, acc[i][2]);
            acc[i][3] = fmaf(xv.x, wv[0].w, acc[i][3]);
            acc[i][0] = fmaf(xv.y, wv[1].x, acc[i][0]);
            acc[i][1] = fmaf(xv.y, wv[1].y, acc[i][1]);
            acc[i][2] = fmaf(xv.y, wv[1].z, acc[i][2]);
            acc[i][3] = fmaf(xv.y, wv[1].w, acc[i][3]);
            acc[i][0] = fmaf(xv.z, wv[2].x, acc[i][0]);
            acc[i][1] = fmaf(xv.z, wv[2].y, acc[i][1]);
            acc[i][2] = fmaf(xv.z, wv[2].z, acc[i][2]);
            acc[i][3] = fmaf(xv.z, wv[2].w, acc[i][3]);
            acc[i][0] = fmaf(xv.w, wv[3].x, acc[i][0]);
            acc[i][1] = fmaf(xv.w, wv[3].y, acc[i][1]);
            acc[i][2] = fmaf(xv.w, wv[3].z, acc[i][2]);
            acc[i][3] = fmaf(xv.w, wv[3].w, acc[i][3]);
        }
    }

    float4 bv = ((const float4*)B)[cg];
    #pragma unroll
    for (int i = 0; i < 8; i++) {
        int r = row0 + rbase + i;
        if (r < n) {
            float sc = postscale ? __ldg(&postscale[r]) : 1.0f;
            float ox = fmaxf(acc[i][0] + bv.x, 0.0f) * sc;
            float oy = fmaxf(acc[i][1] + bv.y, 0.0f) * sc;
            float oz = fmaxf(acc[i][2] + bv.z, 0.0f) * sc;
            float ow = fmaxf(acc[i][3] + bv.w, 0.0f) * sc;
            if (HALF_OUT) {
                __half2 p0 = __floats2half2_rn(ox, oy);
                __half2 p1 = __floats2half2_rn(oz, ow);
                uint2 st;
                st.x = *(uint32_t*)&p0;
                st.y = *(uint32_t*)&p1;
                *(uint2*)((__half*)outv + (long)r * 128 + cg * 4) = st;
            } else {
                *(float4*)((float*)outv + (long)r * 128 + cg * 4) =
                    make_float4(ox, oy, oz, ow);
            }
        }
    }
}

// ---------------- proj GEMM (K=64, fp32 in): h = fp16(relu(x @ Wp + bp) * nsrc) --------------
__global__ void gemm64_kernel(const float* __restrict__ X, const float* __restrict__ W,
                              const float* __restrict__ B,
                              const float* __restrict__ postscale,
                              __half* __restrict__ out, int n) {
    extern __shared__ float sm[];
    float* w_sh = sm;              // 64 * 128
    float* x_sh = sm + 64 * 128;   // 64 * 64

    const int tx = threadIdx.x;
    const int row0 = blockIdx.x * 64;

    {
        const float4* W4 = (const float4*)W;
        float4* w4 = (float4*)w_sh;
        #pragma unroll
        for (int i = tx; i < 64 * 32; i += 256) w4[i] = W4[i];
    }
    {
        const float4* X4 = (const float4*)X;
        float4* x4 = (float4*)x_sh;
        #pragma unroll
        for (int i = tx; i < 64 * 16; i += 256) {
            int r = i >> 4;
            int c = i & 15;
            int gr = row0 + r;
            if (gr >= n) gr = n - 1;
            x4[i] = X4[(long)gr * 16 + c];
        }
    }
    __syncthreads();

    const int cg = tx & 31;
    const int rbase = (tx >> 5) * 8;

    float acc[8][4];
    #pragma unroll
    for (int i = 0; i < 8; i++)
        #pragma unroll
        for (int j = 0; j < 4; j++) acc[i][j] = 0.0f;

    #pragma unroll 2
    for (int k = 0; k < 64; k += 4) {
        float4 wv[4];
        #pragma unroll
        for (int t = 0; t < 4; t++)
            wv[t] = *(const float4*)&w_sh[(k + t) * 128 + cg * 4];
        #pragma unroll
        for (int i = 0; i < 8; i++) {
            float4 xv = *(const float4*)&x_sh[(rbase + i) * 64 + k];
            acc[i][0] = fmaf(xv.x, wv[0].x, acc[i][0]);
            acc[i][1] = fmaf(xv.x, wv[0].y, acc[i][1]);
            acc[i][2] = fmaf(xv.x, wv[0].z, acc[i][2]);
            acc[i][3] = fmaf(xv.x, wv[0].w, acc[i][3]);
            acc[i][0] = fmaf(xv.y, wv[1].x, acc[i][0]);
            acc[i][1] = fmaf(xv.y, wv[1].y, acc[i][1]);
            acc[i][2] = fmaf(xv.y, wv[1].z, acc[i][2]);
            acc[i][3] = fmaf(xv.y, wv[1].w, acc[i][3]);
            acc[i][0] = fmaf(xv.z, wv[2].x, acc[i][0]);
            acc[i][1] = fmaf(xv.z, wv[2].y, acc[i][1]);
            acc[i][2] = fmaf(xv.z, wv[2].z, acc[i][2]);
            acc[i][3] = fmaf(xv.z, wv[2].w, acc[i][3]);
            acc[i][0] = fmaf(xv.w, wv[3].x, acc[i][0]);
            acc[i][1] = fmaf(xv.w, wv[3].y, acc[i][1]);
            acc[i][2] = fmaf(xv.w, wv[3].z, acc[i][2]);
            acc[i][3] = fmaf(xv.w, wv[3].w, acc[i][3]);
        }
    }

    float4 bv = ((const float4*)B)[cg];
    #pragma unroll
    for (int i = 0; i < 8; i++) {
        int r = row0 + rbase + i;
        if (r < n) {
            float sc = __ldg(&postscale[r]);
            float ox = fmaxf(acc[i][0] + bv.x, 0.0f) * sc;
            float oy = fmaxf(acc[i][1] + bv.y, 0.0f) * sc;
            float oz = fmaxf(acc[i][2] + bv.z, 0.0f) * sc;
            float ow = fmaxf(acc[i][3] + bv.w, 0.0f) * sc;
            __half2 p0 = __floats2half2_rn(ox, oy);
            __half2 p1 = __floats2half2_rn(oz, ow);
            uint2 st;
            st.x = *(uint32_t*)&p0;
            st.y = *(uint32_t*)&p1;
            *(uint2*)(out + (long)r * 128 + cg * 4) = st;
        }
    }
}

extern "C" void kernel_launch(void* const* d_in, const int* in_sizes, int n_in,
                              void* d_out, int out_size) {
    const float* x_raw = (const float*)d_in[0];
    const int*   src   = (const int*)d_in[1];
    const int*   dst   = (const int*)d_in[2];
    const float* Wp    = (const float*)d_in[3];
    const float* bp    = (const float*)d_in[4];
    const float* Wl    = (const float*)d_in[5];
    const float* bl    = (const float*)d_in[6];
    float* out = (float*)d_out;

    const int N = in_sizes[0] / 64;
    const int E = in_sizes[1];

    __half *h, *agg;
    float *nsrc, *ndst;
    int *dego, *degi, *off, *cur, *csr, *tsum;
    cudaGetSymbolAddress((void**)&h, g_h);
    cudaGetSymbolAddress((void**)&agg, g_agg);
    cudaGetSymbolAddress((void**)&nsrc, g_nsrc);
    cudaGetSymbolAddress((void**)&ndst, g_ndst);
    cudaGetSymbolAddress((void**)&dego, g_dego);
    cudaGetSymbolAddress((void**)&degi, g_degi);
    cudaGetSymbolAddress((void**)&off, g_off);
    cudaGetSymbolAddress((void**)&cur, g_cur);
    cudaGetSymbolAddress((void**)&csr, g_csr);
    cudaGetSymbolAddress((void**)&tsum, g_tsum);

    const int GEMM128_SMEM = (128 * 128 + 64 * 128) * (int)sizeof(float);
    const int PROJ_SMEM = (64 * 128 + 64 * 64) * (int)sizeof(float);
    cudaFuncSetAttribute((const void*)gemm128_kernel<true>,
                         cudaFuncAttributeMaxDynamicSharedMemorySize, GEMM128_SMEM);
    cudaFuncSetAttribute((const void*)gemm128_kernel<false>,
                         cudaFuncAttributeMaxDynamicSharedMemorySize, GEMM128_SMEM);
    cudaFuncSetAttribute((const void*)gemm64_kernel,
                         cudaFuncAttributeMaxDynamicSharedMemorySize, PROJ_SMEM);

    // 1) degrees -> norms + CSR(by dst)
    const int E4 = E >> 2;
    zero_deg_kernel<<<(N + 255) / 256, 256>>>(dego, degi, N);
    degree_kernel<<<(E4 + 255) / 256, 256>>>(src, dst, dego, degi, E);
    partsum_kernel<<<SCAN_T / 256, 256>>>(degi, tsum, N);
    scanpart_kernel<<<1, 1024>>>(tsum);
    writeoff_kernel<<<SCAN_T / 256, 256>>>(degi, dego, tsum, off, cur, nsrc, ndst, N);
    fill_kernel<<<(E4 + 255) / 256, 256>>>(src, dst, cur, csr, E);

    // 2) h = fp16( relu(x_raw @ Wp + bp) * norm_src )
    gemm64_kernel<<<(N + 63) / 64, 256, PROJ_SMEM>>>(x_raw, Wp, bp, nsrc, h, N);

    // 3) layers: pull (fp16 agg out) then GEMM (fp16 in)
    const int pull_blocks = (N * 32 + 255) / 256;
    const int gblocks = (N + 63) / 64;
    for (int l = 0; l < 3; l++) {
        pull_kernel<<<pull_blocks, 256>>>(off, csr, ndst, (const uint2*)h, (uint2*)agg, N);
        const float* Wcur = Wl + (long)l * 128 * 128;
        const float* bcur = bl + (long)l * 128;
        if (l == 2) {
            gemm128_kernel<false><<<gblocks, 256, GEMM128_SMEM>>>(
                (const uint2*)agg, Wcur, bcur, nullptr, out, N);
        } else {
            gemm128_kernel<true><<<gblocks, 256, GEMM128_SMEM>>>(
                (const uint2*)agg, Wcur, bcur, nsrc, h, N);
        }
    }
}

// round 9
// speedup vs baseline: 2.0216x; 1.5465x over previous
#include <cuda_runtime.h>
#include <cuda_fp16.h>
#include <cstdint>

#define NN 50000
#define EE 800000
#define SCAN_T 2048

// ---------------- scratch (__device__ globals; allocation-free) ----------------
__device__ __half g_h[NN * 128];       // activations fp16 (gather-side)
__device__ __half g_agg[NN * 128];     // SpMM result fp16 (GEMM input)
__device__ float  g_nsrc[NN];
__device__ float  g_ndst[NN];
__device__ int    g_dego[NN];
__device__ int    g_degi[NN];
__device__ int    g_off[NN + 1];
__device__ int    g_cur[NN];
__device__ int    g_csr[EE];
__device__ int    g_tsum[SCAN_T];
__device__ uint2  g_wfrag[3 * 8 * 16 * 32];   // per-lane HMMA B-fragments, 3 layers

// ---------------- f32x2 packed helpers (Blackwell) ----------------
__device__ __forceinline__ unsigned long long pack2(float a, float b) {
    unsigned long long r;
    asm("mov.b64 %0, {%1, %2};" : "=l"(r) : "f"(a), "f"(b));
    return r;
}
__device__ __forceinline__ void unpack2(unsigned long long v, float& a, float& b) {
    asm("mov.b64 {%0, %1}, %2;" : "=f"(a), "=f"(b) : "l"(v));
}
__device__ __forceinline__ void addx2(unsigned long long& acc, unsigned long long v) {
    asm("add.rn.f32x2 %0, %0, %1;" : "+l"(acc) : "l"(v));
}
__device__ __forceinline__ void mulx2(unsigned long long& acc, unsigned long long v) {
    asm("mul.rn.f32x2 %0, %0, %1;" : "+l"(acc) : "l"(v));
}
__device__ __forceinline__ void acc_h2(unsigned long long& a0, unsigned long long& a1,
                                       uint2 v) {
    float2 f;
    f = __half22float2(*(const __half2*)&v.x);
    addx2(a0, pack2(f.x, f.y));
    f = __half22float2(*(const __half2*)&v.y);
    addx2(a1, pack2(f.x, f.y));
}

// mma.sync m16n8k16 row.col f16*f16+f32
__device__ __forceinline__ void hmma(float* c, uint32_t a0, uint32_t a1, uint32_t a2,
                                     uint32_t a3, uint32_t b0, uint32_t b1) {
    asm volatile(
        "mma.sync.aligned.m16n8k16.row.col.f32.f16.f16.f32 "
        "{%0,%1,%2,%3}, {%4,%5,%6,%7}, {%8,%9}, {%0,%1,%2,%3};"
        : "+f"(c[0]), "+f"(c[1]), "+f"(c[2]), "+f"(c[3])
        : "r"(a0), "r"(a1), "r"(a2), "r"(a3), "r"(b0), "r"(b1));
}

// ---------------- CSR build ----------------
__global__ void zero_deg_kernel(int* a, int* b, int n) {
    int i = blockIdx.x * blockDim.x + threadIdx.x;
    if (i < n) { a[i] = 0; b[i] = 0; }
}

__global__ void degree_kernel(const int* __restrict__ src, const int* __restrict__ dst,
                              int* dego, int* degi, int E) {
    int i = blockIdx.x * blockDim.x + threadIdx.x;
    int E4 = E >> 2;
    if (i < E4) {
        int4 s = __ldg((const int4*)src + i);
        int4 d = __ldg((const int4*)dst + i);
        atomicAdd(&dego[s.x], 1);
        atomicAdd(&dego[s.y], 1);
        atomicAdd(&dego[s.z], 1);
        atomicAdd(&dego[s.w], 1);
        atomicAdd(&degi[d.x], 1);
        atomicAdd(&degi[d.y], 1);
        atomicAdd(&degi[d.z], 1);
        atomicAdd(&degi[d.w], 1);
    }
    if (i == 0) {
        for (int e = E4 << 2; e < E; e++) {
            atomicAdd(&dego[src[e]], 1);
            atomicAdd(&degi[dst[e]], 1);
        }
    }
}

__global__ void partsum_kernel(const int* __restrict__ degi, int* tsum, int N) {
    int t = blockIdx.x * blockDim.x + threadIdx.x;
    if (t >= SCAN_T) return;
    int chunk = (N + SCAN_T - 1) / SCAN_T;
    int b = t * chunk, e = min(b + chunk, N);
    int s = 0;
    for (int i = b; i < e; i++) s += degi[i];
    tsum[t] = s;
}

__global__ void scanpart_kernel(int* tsum) {
    __shared__ int sm[1024];
    int t = threadIdx.x;
    int a = tsum[2 * t], b = tsum[2 * t + 1];
    sm[t] = a + b;
    __syncthreads();
    for (int d = 1; d < 1024; d <<= 1) {
        int v = (t >= d) ? sm[t - d] : 0;
        __syncthreads();
        sm[t] += v;
        __syncthreads();
    }
    int excl = (t > 0) ? sm[t - 1] : 0;
    tsum[2 * t] = excl;
    tsum[2 * t + 1] = excl + a;
}

__global__ void writeoff_kernel(const int* __restrict__ degi, const int* __restrict__ dego,
                                const int* __restrict__ tsum,
                                int* off, int* cur, float* nsrc, float* ndst, int N) {
    int t = blockIdx.x * blockDim.x + threadIdx.x;
    if (t >= SCAN_T) return;
    int chunk = (N + SCAN_T - 1) / SCAN_T;
    int b = t * chunk, e = min(b + chunk, N);
    int run = tsum[t];
    for (int i = b; i < e; i++) {
        off[i] = run;
        cur[i] = run;
        int di = degi[i];
        run += di;
        ndst[i] = rsqrtf((float)max(di, 1));
        nsrc[i] = rsqrtf((float)max(dego[i], 1));
    }
    if (t == SCAN_T - 1) off[N] = run;
}

__global__ void fill_kernel(const int* __restrict__ src, const int* __restrict__ dst,
                            int* cur, int* csr, int E) {
    int i = blockIdx.x * blockDim.x + threadIdx.x;
    int E4 = E >> 2;
    if (i < E4) {
        int4 s = __ldg((const int4*)src + i);
        int4 d = __ldg((const int4*)dst + i);
        int p0 = atomicAdd(&cur[d.x], 1);
        int p1 = atomicAdd(&cur[d.y], 1);
        int p2 = atomicAdd(&cur[d.z], 1);
        int p3 = atomicAdd(&cur[d.w], 1);
        csr[p0] = s.x;
        csr[p1] = s.y;
        csr[p2] = s.z;
        csr[p3] = s.w;
    }
    if (i == 0) {
        for (int e = E4 << 2; e < E; e++) {
            int p = atomicAdd(&cur[dst[e]], 1);
            csr[p] = src[e];
        }
    }
}

// ---------------- weight fragment prep: W[k][n] fp32 -> per-lane HMMA B frags ------------
// frag[l][kt][nt][lane] = uint2{ half2(W[k0][n],W[k0+1][n]), half2(W[k0+8][n],W[k0+9][n]) }
// where k0 = kt*16 + (lane%4)*2, n = nt*8 + lane/4.
__global__ void prep_wfrag_kernel(const float* __restrict__ Wl, uint2* __restrict__ frag) {
    int i = blockIdx.x * blockDim.x + threadIdx.x;
    if (i >= 3 * 8 * 16 * 32) return;
    int lane = i & 31;
    int nt = (i >> 5) & 15;
    int kt = (i >> 9) & 7;
    int l = i >> 12;
    const float* W = Wl + l * 16384;
    int n = nt * 8 + (lane >> 2);
    int k0 = kt * 16 + (lane & 3) * 2;
    __half2 b0 = __floats2half2_rn(W[k0 * 128 + n], W[(k0 + 1) * 128 + n]);
    __half2 b1 = __floats2half2_rn(W[(k0 + 8) * 128 + n], W[(k0 + 9) * 128 + n]);
    uint2 u;
    u.x = *(uint32_t*)&b0;
    u.y = *(uint32_t*)&b1;
    frag[i] = u;
}

// ---------------- pull SpMM: agg[d] = fp16( ndst[d] * sum_{s in in(d)} h[s] ) -----------
__global__ void pull_kernel(const int* __restrict__ off, const int* __restrict__ csr,
                            const float* __restrict__ ndst,
                            const uint2* __restrict__ h2, uint2* __restrict__ agg2, int N) {
    int w = (blockIdx.x * blockDim.x + threadIdx.x) >> 5;
    int lane = threadIdx.x & 31;
    if (w >= N) return;
    int beg = __ldg(&off[w]);
    int end = __ldg(&off[w + 1]);

    unsigned long long a0 = pack2(0.f, 0.f), a1 = a0;

    int j = beg;
    for (; j + 8 <= end; j += 8) {
        int s0 = __ldg(&csr[j]);
        int s1 = __ldg(&csr[j + 1]);
        int s2 = __ldg(&csr[j + 2]);
        int s3 = __ldg(&csr[j + 3]);
        int s4 = __ldg(&csr[j + 4]);
        int s5 = __ldg(&csr[j + 5]);
        int s6 = __ldg(&csr[j + 6]);
        int s7 = __ldg(&csr[j + 7]);
        uint2 v0 = __ldg(&h2[(long)s0 * 32 + lane]);
        uint2 v1 = __ldg(&h2[(long)s1 * 32 + lane]);
        uint2 v2 = __ldg(&h2[(long)s2 * 32 + lane]);
        uint2 v3 = __ldg(&h2[(long)s3 * 32 + lane]);
        uint2 v4 = __ldg(&h2[(long)s4 * 32 + lane]);
        uint2 v5 = __ldg(&h2[(long)s5 * 32 + lane]);
        uint2 v6 = __ldg(&h2[(long)s6 * 32 + lane]);
        uint2 v7 = __ldg(&h2[(long)s7 * 32 + lane]);
        acc_h2(a0, a1, v0);
        acc_h2(a0, a1, v1);
        acc_h2(a0, a1, v2);
        acc_h2(a0, a1, v3);
        acc_h2(a0, a1, v4);
        acc_h2(a0, a1, v5);
        acc_h2(a0, a1, v6);
        acc_h2(a0, a1, v7);
    }
    for (; j < end; j++) {
        int s = __ldg(&csr[j]);
        acc_h2(a0, a1, __ldg(&h2[(long)s * 32 + lane]));
    }

    float nd = __ldg(&ndst[w]);
    unsigned long long nn = pack2(nd, nd);
    mulx2(a0, nn);
    mulx2(a1, nn);
    float4 o;
    unpack2(a0, o.x, o.y);
    unpack2(a1, o.z, o.w);
    __half2 p0 = __floats2half2_rn(o.x, o.y);
    __half2 p1 = __floats2half2_rn(o.z, o.w);
    uint2 st;
    st.x = *(uint32_t*)&p0;
    st.y = *(uint32_t*)&p1;
    agg2[(long)w * 32 + lane] = st;
}

// ---------------- HMMA GEMM: out = relu(X(fp16) @ W(fp16 frags) + bias) * postscale ------
// Block: 256 threads = 8 warps; 128 rows x 128 cols. Warp: 16 rows x 128 cols.
// smem: X tile 128 x 136 halves (16B pad -> conflict-free A-frag LDS) + W frags 32KB.
#define XPAD 136
template <bool HALF_OUT>
__global__ void __launch_bounds__(256, 2)
gemm_mma_kernel(const uint2* __restrict__ X2, const uint2* __restrict__ Wfrag,
                const float* __restrict__ B, const float* __restrict__ postscale,
                void* __restrict__ outv, int n) {
    extern __shared__ char smraw[];
    __half* x_sh = (__half*)smraw;                         // 128*136*2 = 34816 B
    uint2* w_sh = (uint2*)(smraw + 128 * XPAD * 2);        // 4096 uint2 = 32768 B

    const int tx = threadIdx.x;
    const int row0 = blockIdx.x * 128;

    // stage W fragments (coalesced)
    #pragma unroll
    for (int i = tx; i < 4096; i += 256) w_sh[i] = __ldg(&Wfrag[i]);
    // stage X tile: 128 rows x 32 uint2 (fp16x4), padded rows
    #pragma unroll
    for (int i = tx; i < 4096; i += 256) {
        int r = i >> 5, c = i & 31;
        int gr = row0 + r;
        if (gr >= n) gr = n - 1;
        uint2 v = __ldg(&X2[(long)gr * 32 + c]);
        *(uint2*)&x_sh[r * XPAD + c * 4] = v;
    }
    __syncthreads();

    const int w = tx >> 5;
    const int lane = tx & 31;
    const int rq = lane >> 2;       // 0..7
    const int kq = (lane & 3) * 2;  // 0,2,4,6

    float c[16][4];
    #pragma unroll
    for (int nt = 0; nt < 16; nt++)
        #pragma unroll
        for (int q = 0; q < 4; q++) c[nt][q] = 0.0f;

    #pragma unroll
    for (int kt = 0; kt < 8; kt++) {
        const __half* arow0 = &x_sh[(w * 16 + rq) * XPAD + kt * 16 + kq];
        const __half* arow1 = arow0 + 8 * XPAD;
        uint32_t a0 = *(const uint32_t*)arow0;
        uint32_t a1 = *(const uint32_t*)arow1;
        uint32_t a2 = *(const uint32_t*)(arow0 + 8);
        uint32_t a3 = *(const uint32_t*)(arow1 + 8);
        #pragma unroll
        for (int nt = 0; nt < 16; nt++) {
            uint2 b = w_sh[(kt * 16 + nt) * 32 + lane];
            hmma(c[nt], a0, a1, a2, a3, b.x, b.y);
        }
    }

    // epilogue: thread owns rows r0, r0+8 at cols nt*8 + kq (+1)
    int r0 = row0 + w * 16 + rq;
    int r1 = r0 + 8;
    float sc0 = 1.0f, sc1 = 1.0f;
    if (postscale) {
        if (r0 < n) sc0 = __ldg(&postscale[r0]);
        if (r1 < n) sc1 = __ldg(&postscale[r1]);
    }
    #pragma unroll
    for (int nt = 0; nt < 16; nt++) {
        int col = nt * 8 + kq;
        float2 bv = *(const float2*)&B[col];
        float o00 = fmaxf(c[nt][0] + bv.x, 0.0f) * sc0;
        float o01 = fmaxf(c[nt][1] + bv.y, 0.0f) * sc0;
        float o10 = fmaxf(c[nt][2] + bv.x, 0.0f) * sc1;
        float o11 = fmaxf(c[nt][3] + bv.y, 0.0f) * sc1;
        if (HALF_OUT) {
            if (r0 < n) {
                __half2 p = __floats2half2_rn(o00, o01);
                *(uint32_t*)((__half*)outv + (long)r0 * 128 + col) = *(uint32_t*)&p;
            }
            if (r1 < n) {
                __half2 p = __floats2half2_rn(o10, o11);
                *(uint32_t*)((__half*)outv + (long)r1 * 128 + col) = *(uint32_t*)&p;
            }
        } else {
            if (r0 < n)
                *(float2*)((float*)outv + (long)r0 * 128 + col) = make_float2(o00, o01);
            if (r1 < n)
                *(float2*)((float*)outv + (long)r1 * 128 + col) = make_float2(o10, o11);
        }
    }
}

// ---------------- proj GEMM (K=64, fp32 exact): h = fp16(relu(x @ Wp + bp) * nsrc) -------
__global__ void gemm64_kernel(const float* __restrict__ X, const float* __restrict__ W,
                              const float* __restrict__ B,
                              const float* __restrict__ postscale,
                              __half* __restrict__ out, int n) {
    extern __shared__ float sm[];
    float* w_sh = sm;              // 64 * 128
    float* x_sh = sm + 64 * 128;   // 64 * 64

    const int tx = threadIdx.x;
    const int row0 = blockIdx.x * 64;

    {
        const float4* W4 = (const float4*)W;
        float4* w4 = (float4*)w_sh;
        #pragma unroll
        for (int i = tx; i < 64 * 32; i += 256) w4[i] = W4[i];
    }
    {
        const float4* X4 = (const float4*)X;
        float4* x4 = (float4*)x_sh;
        #pragma unroll
        for (int i = tx; i < 64 * 16; i += 256) {
            int r = i >> 4;
            int c = i & 15;
            int gr = row0 + r;
            if (gr >= n) gr = n - 1;
            x4[i] = X4[(long)gr * 16 + c];
        }
    }
    __syncthreads();

    const int cg = tx & 31;
    const int rbase = (tx >> 5) * 8;

    float acc[8][4];
    #pragma unroll
    for (int i = 0; i < 8; i++)
        #pragma unroll
        for (int j = 0; j < 4; j++) acc[i][j] = 0.0f;

    #pragma unroll 2
    for (int k = 0; k < 64; k += 4) {
        float4 wv[4];
        #pragma unroll
        for (int t = 0; t < 4; t++)
            wv[t] = *(const float4*)&w_sh[(k + t) * 128 + cg * 4];
        #pragma unroll
        for (int i = 0; i < 8; i++) {
            float4 xv = *(const float4*)&x_sh[(rbase + i) * 64 + k];
            acc[i][0] = fmaf(xv.x, wv[0].x, acc[i][0]);
            acc[i][1] = fmaf(xv.x, wv[0].y, acc[i][1]);
            acc[i][2] = fmaf(xv.x, wv[0].z, acc[i][2]);
            acc[i][3] = fmaf(xv.x, wv[0].w, acc[i][3]);
            acc[i][0] = fmaf(xv.y, wv[1].x, acc[i][0]);
            acc[i][1] = fmaf(xv.y, wv[1].y, acc[i][1]);
            acc[i][2] = fmaf(xv.y, wv[1].z, acc[i][2]);
            acc[i][3] = fmaf(xv.y, wv[1].w, acc[i][3]);
            acc[i][0] = fmaf(xv.z, wv[2].x, acc[i][0]);
            acc[i][1] = fmaf(xv.z, wv[2].y, acc[i][1]);
            acc[i][2] = fmaf(xv.z, wv[2].z, acc[i][2]);
            acc[i][3] = fmaf(xv.z, wv[2].w, acc[i][3]);
            acc[i][0] = fmaf(xv.w, wv[3].x, acc[i][0]);
            acc[i][1] = fmaf(xv.w, wv[3].y, acc[i][1]);
            acc[i][2] = fmaf(xv.w, wv[3].z, acc[i][2]);
            acc[i][3] = fmaf(xv.w, wv[3].w, acc[i][3]);
        }
    }

    float4 bv = ((const float4*)B)[cg];
    #pragma unroll
    for (int i = 0; i < 8; i++) {
        int r = row0 + rbase + i;
        if (r < n) {
            float sc = __ldg(&postscale[r]);
            float ox = fmaxf(acc[i][0] + bv.x, 0.0f) * sc;
            float oy = fmaxf(acc[i][1] + bv.y, 0.0f) * sc;
            float oz = fmaxf(acc[i][2] + bv.z, 0.0f) * sc;
            float ow = fmaxf(acc[i][3] + bv.w, 0.0f) * sc;
            __half2 p0 = __floats2half2_rn(ox, oy);
            __half2 p1 = __floats2half2_rn(oz, ow);
            uint2 st;
            st.x = *(uint32_t*)&p0;
            st.y = *(uint32_t*)&p1;
            *(uint2*)(out + (long)r * 128 + cg * 4) = st;
        }
    }
}

extern "C" void kernel_launch(void* const* d_in, const int* in_sizes, int n_in,
                              void* d_out, int out_size) {
    const float* x_raw = (const float*)d_in[0];
    const int*   src   = (const int*)d_in[1];
    const int*   dst   = (const int*)d_in[2];
    const float* Wp    = (const float*)d_in[3];
    const float* bp    = (const float*)d_in[4];
    const float* Wl    = (const float*)d_in[5];
    const float* bl    = (const float*)d_in[6];
    float* out = (float*)d_out;

    const int N = in_sizes[0] / 64;
    const int E = in_sizes[1];

    __half *h, *agg;
    float *nsrc, *ndst;
    int *dego, *degi, *off, *cur, *csr, *tsum;
    uint2* wfrag;
    cudaGetSymbolAddress((void**)&h, g_h);
    cudaGetSymbolAddress((void**)&agg, g_agg);
    cudaGetSymbolAddress((void**)&nsrc, g_nsrc);
    cudaGetSymbolAddress((void**)&ndst, g_ndst);
    cudaGetSymbolAddress((void**)&dego, g_dego);
    cudaGetSymbolAddress((void**)&degi, g_degi);
    cudaGetSymbolAddress((void**)&off, g_off);
    cudaGetSymbolAddress((void**)&cur, g_cur);
    cudaGetSymbolAddress((void**)&csr, g_csr);
    cudaGetSymbolAddress((void**)&tsum, g_tsum);
    cudaGetSymbolAddress((void**)&wfrag, g_wfrag);

    const int MMA_SMEM = 128 * XPAD * 2 + 4096 * 8;   // 34816 + 32768 = 67584
    const int PROJ_SMEM = (64 * 128 + 64 * 64) * (int)sizeof(float);
    cudaFuncSetAttribute((const void*)gemm_mma_kernel<true>,
                         cudaFuncAttributeMaxDynamicSharedMemorySize, MMA_SMEM);
    cudaFuncSetAttribute((const void*)gemm_mma_kernel<false>,
                         cudaFuncAttributeMaxDynamicSharedMemorySize, MMA_SMEM);
    cudaFuncSetAttribute((const void*)gemm64_kernel,
                         cudaFuncAttributeMaxDynamicSharedMemorySize, PROJ_SMEM);

    // 0) weight fragment prep (independent)
    prep_wfrag_kernel<<<(3 * 8 * 16 * 32 + 255) / 256, 256>>>(Wl, wfrag);

    // 1) degrees -> norms + CSR(by dst)
    const int E4 = E >> 2;
    zero_deg_kernel<<<(N + 255) / 256, 256>>>(dego, degi, N);
    degree_kernel<<<(E4 + 255) / 256, 256>>>(src, dst, dego, degi, E);
    partsum_kernel<<<SCAN_T / 256, 256>>>(degi, tsum, N);
    scanpart_kernel<<<1, 1024>>>(tsum);
    writeoff_kernel<<<SCAN_T / 256, 256>>>(degi, dego, tsum, off, cur, nsrc, ndst, N);
    fill_kernel<<<(E4 + 255) / 256, 256>>>(src, dst, cur, csr, E);

    // 2) h = fp16( relu(x_raw @ Wp + bp) * norm_src )
    gemm64_kernel<<<(N + 63) / 64, 256, PROJ_SMEM>>>(x_raw, Wp, bp, nsrc, h, N);

    // 3) layers: pull (fp16 agg) then HMMA GEMM
    const int pull_blocks = (N * 32 + 255) / 256;
    const int mma_blocks = (N + 127) / 128;
    for (int l = 0; l < 3; l++) {
        pull_kernel<<<pull_blocks, 256>>>(off, csr, ndst, (const uint2*)h, (uint2*)agg, N);
        const uint2* wf = wfrag + (long)l * 4096;
        const float* bcur = bl + (long)l * 128;
        if (l == 2) {
            gemm_mma_kernel<false><<<mma_blocks, 256, MMA_SMEM>>>(
                (const uint2*)agg, wf, bcur, nullptr, out, N);
        } else {
            gemm_mma_kernel<true><<<mma_blocks, 256, MMA_SMEM>>>(
                (const uint2*)agg, wf, bcur, nsrc, h, N);
        }
    }
}

// round 10
// speedup vs baseline: 2.2153x; 1.0958x over previous
#include <cuda_runtime.h>
#include <cuda_fp16.h>
#include <cstdint>

#define NN 50000
#define EE 800000
#define SCAN_T 2048

// ---------------- scratch (__device__ globals; allocation-free) ----------------
__device__ __half g_h[NN * 128];       // activations fp16 (gather-side)
__device__ __half g_agg[NN * 128];     // SpMM result fp16 (GEMM input)
__device__ float  g_nsrc[NN];
__device__ float  g_ndst[NN];
__device__ int    g_dego[NN];
__device__ int    g_degi[NN];
__device__ int    g_off[NN + 1];
__device__ int    g_cur[NN];
__device__ int    g_csr[EE];
__device__ int    g_tsum[SCAN_T];
__device__ uint2  g_wfrag[3 * 4096 + 2048];   // HMMA B-frags: 3 layers + proj

// ---------------- f32x2 packed helpers (Blackwell) ----------------
__device__ __forceinline__ unsigned long long pack2(float a, float b) {
    unsigned long long r;
    asm("mov.b64 %0, {%1, %2};" : "=l"(r) : "f"(a), "f"(b));
    return r;
}
__device__ __forceinline__ void unpack2(unsigned long long v, float& a, float& b) {
    asm("mov.b64 {%0, %1}, %2;" : "=f"(a), "=f"(b) : "l"(v));
}
__device__ __forceinline__ void addx2(unsigned long long& acc, unsigned long long v) {
    asm("add.rn.f32x2 %0, %0, %1;" : "+l"(acc) : "l"(v));
}
__device__ __forceinline__ void mulx2(unsigned long long& acc, unsigned long long v) {
    asm("mul.rn.f32x2 %0, %0, %1;" : "+l"(acc) : "l"(v));
}
__device__ __forceinline__ void acc_h2(unsigned long long& a0, unsigned long long& a1,
                                       uint2 v) {
    float2 f;
    f = __half22float2(*(const __half2*)&v.x);
    addx2(a0, pack2(f.x, f.y));
    f = __half22float2(*(const __half2*)&v.y);
    addx2(a1, pack2(f.x, f.y));
}

// mma.sync m16n8k16 row.col f16*f16+f32
__device__ __forceinline__ void hmma(float* c, uint32_t a0, uint32_t a1, uint32_t a2,
                                     uint32_t a3, uint32_t b0, uint32_t b1) {
    asm volatile(
        "mma.sync.aligned.m16n8k16.row.col.f32.f16.f16.f32 "
        "{%0,%1,%2,%3}, {%4,%5,%6,%7}, {%8,%9}, {%0,%1,%2,%3};"
        : "+f"(c[0]), "+f"(c[1]), "+f"(c[2]), "+f"(c[3])
        : "r"(a0), "r"(a1), "r"(a2), "r"(a3), "r"(b0), "r"(b1));
}

// ---------------- CSR build ----------------
__global__ void zero_deg_kernel(int* a, int* b, int n) {
    int i = blockIdx.x * blockDim.x + threadIdx.x;
    if (i < n) { a[i] = 0; b[i] = 0; }
}

__global__ void degree_kernel(const int* __restrict__ src, const int* __restrict__ dst,
                              int* dego, int* degi, int E) {
    int i = blockIdx.x * blockDim.x + threadIdx.x;
    int E4 = E >> 2;
    if (i < E4) {
        int4 s = __ldg((const int4*)src + i);
        int4 d = __ldg((const int4*)dst + i);
        atomicAdd(&dego[s.x], 1);
        atomicAdd(&dego[s.y], 1);
        atomicAdd(&dego[s.z], 1);
        atomicAdd(&dego[s.w], 1);
        atomicAdd(&degi[d.x], 1);
        atomicAdd(&degi[d.y], 1);
        atomicAdd(&degi[d.z], 1);
        atomicAdd(&degi[d.w], 1);
    }
    if (i == 0) {
        for (int e = E4 << 2; e < E; e++) {
            atomicAdd(&dego[src[e]], 1);
            atomicAdd(&degi[dst[e]], 1);
        }
    }
}

// 5 independent accumulators (chunk=25 -> exactly 5 iters, no serial load chain)
__global__ void partsum_kernel(const int* __restrict__ degi, int* tsum, int N) {
    int t = blockIdx.x * blockDim.x + threadIdx.x;
    if (t >= SCAN_T) return;
    int chunk = (N + SCAN_T - 1) / SCAN_T;
    int b = t * chunk, e = min(b + chunk, N);
    int s0 = 0, s1 = 0, s2 = 0, s3 = 0, s4 = 0;
    int i = b;
    for (; i + 5 <= e; i += 5) {
        s0 += degi[i];
        s1 += degi[i + 1];
        s2 += degi[i + 2];
        s3 += degi[i + 3];
        s4 += degi[i + 4];
    }
    for (; i < e; i++) s0 += degi[i];
    tsum[t] = s0 + s1 + s2 + s3 + s4;
}

// shfl-based exclusive scan of 2048 partials (1024 threads, 2 vals each)
__global__ void scanpart_kernel(int* tsum) {
    __shared__ int warpsum[32];
    int t = threadIdx.x;
    int lane = t & 31, wid = t >> 5;
    int a = tsum[2 * t], b = tsum[2 * t + 1];
    int v = a + b;
    int inc = v;
    #pragma unroll
    for (int d = 1; d < 32; d <<= 1) {
        int u = __shfl_up_sync(0xffffffffu, inc, d);
        if (lane >= d) inc += u;
    }
    if (lane == 31) warpsum[wid] = inc;
    __syncthreads();
    if (wid == 0) {
        int w = warpsum[lane];
        int wi = w;
        #pragma unroll
        for (int d = 1; d < 32; d <<= 1) {
            int u = __shfl_up_sync(0xffffffffu, wi, d);
            if (lane >= d) wi += u;
        }
        warpsum[lane] = wi - w;   // exclusive warp offset
    }
    __syncthreads();
    int excl = inc - v + warpsum[wid];
    tsum[2 * t] = excl;
    tsum[2 * t + 1] = excl + a;
}

__global__ void writeoff_kernel(const int* __restrict__ degi, const int* __restrict__ dego,
                                const int* __restrict__ tsum,
                                int* off, int* cur, float* nsrc, float* ndst, int N) {
    int t = blockIdx.x * blockDim.x + threadIdx.x;
    if (t >= SCAN_T) return;
    int chunk = (N + SCAN_T - 1) / SCAN_T;
    int b = t * chunk, e = min(b + chunk, N);
    int run = tsum[t];
    for (int i = b; i < e; i++) {
        off[i] = run;
        cur[i] = run;
        int di = degi[i];
        run += di;
        ndst[i] = rsqrtf((float)max(di, 1));
        nsrc[i] = rsqrtf((float)max(dego[i], 1));
    }
    if (t == SCAN_T - 1) off[N] = run;
}

__global__ void fill_kernel(const int* __restrict__ src, const int* __restrict__ dst,
                            int* cur, int* csr, int E) {
    int i = blockIdx.x * blockDim.x + threadIdx.x;
    int E4 = E >> 2;
    if (i < E4) {
        int4 s = __ldg((const int4*)src + i);
        int4 d = __ldg((const int4*)dst + i);
        int p0 = atomicAdd(&cur[d.x], 1);
        int p1 = atomicAdd(&cur[d.y], 1);
        int p2 = atomicAdd(&cur[d.z], 1);
        int p3 = atomicAdd(&cur[d.w], 1);
        csr[p0] = s.x;
        csr[p1] = s.y;
        csr[p2] = s.z;
        csr[p3] = s.w;
    }
    if (i == 0) {
        for (int e = E4 << 2; e < E; e++) {
            int p = atomicAdd(&cur[dst[e]], 1);
            csr[p] = src[e];
        }
    }
}

// ---------------- weight fragment prep ----------------
// Layers (i<12288): frag[l][kt][nt][lane] from Wl[l] (128x128).
// Proj (i>=12288): frag[kt][nt][lane] from Wp (64x128), kt<4.
__global__ void prep_wfrag_kernel(const float* __restrict__ Wp, const float* __restrict__ Wl,
                                  uint2* __restrict__ frag) {
    int i = blockIdx.x * blockDim.x + threadIdx.x;
    if (i >= 3 * 4096 + 2048) return;
    const float* W;
    int lane, nt, kt;
    if (i < 12288) {
        lane = i & 31;
        nt = (i >> 5) & 15;
        kt = (i >> 9) & 7;
        W = Wl + (i >> 12) * 16384;
    } else {
        int j = i - 12288;
        lane = j & 31;
        nt = (j >> 5) & 15;
        kt = j >> 9;          // 0..3
        W = Wp;
    }
    int n = nt * 8 + (lane >> 2);
    int k0 = kt * 16 + (lane & 3) * 2;
    __half2 b0 = __floats2half2_rn(W[k0 * 128 + n], W[(k0 + 1) * 128 + n]);
    __half2 b1 = __floats2half2_rn(W[(k0 + 8) * 128 + n], W[(k0 + 9) * 128 + n]);
    uint2 u;
    u.x = *(uint32_t*)&b0;
    u.y = *(uint32_t*)&b1;
    frag[i] = u;
}

// ---------------- pull SpMM: agg[d] = fp16( ndst[d] * sum_{s in in(d)} h[s] ) -----------
// Dual accumulator pairs shorten the FADD2 dependency chain.
__global__ void pull_kernel(const int* __restrict__ off, const int* __restrict__ csr,
                            const float* __restrict__ ndst,
                            const uint2* __restrict__ h2, uint2* __restrict__ agg2, int N) {
    int w = (blockIdx.x * blockDim.x + threadIdx.x) >> 5;
    int lane = threadIdx.x & 31;
    if (w >= N) return;
    int beg = __ldg(&off[w]);
    int end = __ldg(&off[w + 1]);

    unsigned long long a0 = pack2(0.f, 0.f), a1 = a0, b0 = a0, b1 = a0;

    int j = beg;
    for (; j + 8 <= end; j += 8) {
        int s0 = __ldg(&csr[j]);
        int s1 = __ldg(&csr[j + 1]);
        int s2 = __ldg(&csr[j + 2]);
        int s3 = __ldg(&csr[j + 3]);
        int s4 = __ldg(&csr[j + 4]);
        int s5 = __ldg(&csr[j + 5]);
        int s6 = __ldg(&csr[j + 6]);
        int s7 = __ldg(&csr[j + 7]);
        uint2 v0 = __ldg(&h2[(long)s0 * 32 + lane]);
        uint2 v1 = __ldg(&h2[(long)s1 * 32 + lane]);
        uint2 v2 = __ldg(&h2[(long)s2 * 32 + lane]);
        uint2 v3 = __ldg(&h2[(long)s3 * 32 + lane]);
        uint2 v4 = __ldg(&h2[(long)s4 * 32 + lane]);
        uint2 v5 = __ldg(&h2[(long)s5 * 32 + lane]);
        uint2 v6 = __ldg(&h2[(long)s6 * 32 + lane]);
        uint2 v7 = __ldg(&h2[(long)s7 * 32 + lane]);
        acc_h2(a0, a1, v0);
        acc_h2(b0, b1, v1);
        acc_h2(a0, a1, v2);
        acc_h2(b0, b1, v3);
        acc_h2(a0, a1, v4);
        acc_h2(b0, b1, v5);
        acc_h2(a0, a1, v6);
        acc_h2(b0, b1, v7);
    }
    for (; j < end; j++) {
        int s = __ldg(&csr[j]);
        acc_h2(a0, a1, __ldg(&h2[(long)s * 32 + lane]));
    }
    addx2(a0, b0);
    addx2(a1, b1);

    float nd = __ldg(&ndst[w]);
    unsigned long long nn = pack2(nd, nd);
    mulx2(a0, nn);
    mulx2(a1, nn);
    float4 o;
    unpack2(a0, o.x, o.y);
    unpack2(a1, o.z, o.w);
    __half2 p0 = __floats2half2_rn(o.x, o.y);
    __half2 p1 = __floats2half2_rn(o.z, o.w);
    uint2 st;
    st.x = *(uint32_t*)&p0;
    st.y = *(uint32_t*)&p1;
    agg2[(long)w * 32 + lane] = st;
}

// ---------------- HMMA GEMM: out = relu(X @ W + bias) * postscale ----------------
// KTILES: K/16. FP32IN: X is fp32 (converted to fp16 while staging) else fp16.
// Block: 256 threads = 8 warps; 128 rows x 128 cols; warp = 16 rows.
// X smem row padded +8 halves -> conflict-free A-frag LDS.32.
template <int KTILES, bool FP32IN, bool HALF_OUT>
__global__ void __launch_bounds__(256, 2)
gemm_mma_kernel(const void* __restrict__ Xv, const uint2* __restrict__ Wfrag,
                const float* __restrict__ B, const float* __restrict__ postscale,
                void* __restrict__ outv, int n) {
    constexpr int XPADH = KTILES * 16 + 8;
    constexpr int C4 = KTILES * 4;           // 4-half chunks per row
    extern __shared__ char smraw[];
    __half* x_sh = (__half*)smraw;                        // 128*XPADH*2 bytes
    uint2* w_sh = (uint2*)(smraw + 128 * XPADH * 2);      // KTILES*512 uint2

    const int tx = threadIdx.x;
    const int row0 = blockIdx.x * 128;

    #pragma unroll
    for (int i = tx; i < KTILES * 512; i += 256) w_sh[i] = __ldg(&Wfrag[i]);

    #pragma unroll
    for (int i = tx; i < 128 * C4; i += 256) {
        int r = i / C4, c = i % C4;
        int gr = row0 + r;
        if (gr >= n) gr = n - 1;
        uint2 v;
        if (FP32IN) {
            float4 f = __ldg((const float4*)Xv + (long)gr * C4 + c);
            __half2 h0 = __floats2half2_rn(f.x, f.y);
            __half2 h1 = __floats2half2_rn(f.z, f.w);
            v.x = *(uint32_t*)&h0;
            v.y = *(uint32_t*)&h1;
        } else {
            v = __ldg((const uint2*)Xv + (long)gr * C4 + c);
        }
        *(uint2*)&x_sh[r * XPADH + c * 4] = v;
    }
    __syncthreads();

    const int w = tx >> 5;
    const int lane = tx & 31;
    const int rq = lane >> 2;       // 0..7
    const int kq = (lane & 3) * 2;  // 0,2,4,6

    float c[16][4];
    #pragma unroll
    for (int nt = 0; nt < 16; nt++)
        #pragma unroll
        for (int q = 0; q < 4; q++) c[nt][q] = 0.0f;

    #pragma unroll
    for (int kt = 0; kt < KTILES; kt++) {
        const __half* arow0 = &x_sh[(w * 16 + rq) * XPADH + kt * 16 + kq];
        const __half* arow1 = arow0 + 8 * XPADH;
        uint32_t a0 = *(const uint32_t*)arow0;
        uint32_t a1 = *(const uint32_t*)arow1;
        uint32_t a2 = *(const uint32_t*)(arow0 + 8);
        uint32_t a3 = *(const uint32_t*)(arow1 + 8);
        #pragma unroll
        for (int nt = 0; nt < 16; nt++) {
            uint2 b = w_sh[(kt * 16 + nt) * 32 + lane];
            hmma(c[nt], a0, a1, a2, a3, b.x, b.y);
        }
    }

    int r0 = row0 + w * 16 + rq;
    int r1 = r0 + 8;
    float sc0 = 1.0f, sc1 = 1.0f;
    if (postscale) {
        if (r0 < n) sc0 = __ldg(&postscale[r0]);
        if (r1 < n) sc1 = __ldg(&postscale[r1]);
    }
    #pragma unroll
    for (int nt = 0; nt < 16; nt++) {
        int col = nt * 8 + kq;
        float2 bv = *(const float2*)&B[col];
        float o00 = fmaxf(c[nt][0] + bv.x, 0.0f) * sc0;
        float o01 = fmaxf(c[nt][1] + bv.y, 0.0f) * sc0;
        float o10 = fmaxf(c[nt][2] + bv.x, 0.0f) * sc1;
        float o11 = fmaxf(c[nt][3] + bv.y, 0.0f) * sc1;
        if (HALF_OUT) {
            if (r0 < n) {
                __half2 p = __floats2half2_rn(o00, o01);
                *(uint32_t*)((__half*)outv + (long)r0 * 128 + col) = *(uint32_t*)&p;
            }
            if (r1 < n) {
                __half2 p = __floats2half2_rn(o10, o11);
                *(uint32_t*)((__half*)outv + (long)r1 * 128 + col) = *(uint32_t*)&p;
            }
        } else {
            if (r0 < n)
                *(float2*)((float*)outv + (long)r0 * 128 + col) = make_float2(o00, o01);
            if (r1 < n)
                *(float2*)((float*)outv + (long)r1 * 128 + col) = make_float2(o10, o11);
        }
    }
}

extern "C" void kernel_launch(void* const* d_in, const int* in_sizes, int n_in,
                              void* d_out, int out_size) {
    const float* x_raw = (const float*)d_in[0];
    const int*   src   = (const int*)d_in[1];
    const int*   dst   = (const int*)d_in[2];
    const float* Wp    = (const float*)d_in[3];
    const float* bp    = (const float*)d_in[4];
    const float* Wl    = (const float*)d_in[5];
    const float* bl    = (const float*)d_in[6];
    float* out = (float*)d_out;

    const int N = in_sizes[0] / 64;
    const int E = in_sizes[1];

    __half *h, *agg;
    float *nsrc, *ndst;
    int *dego, *degi, *off, *cur, *csr, *tsum;
    uint2* wfrag;
    cudaGetSymbolAddress((void**)&h, g_h);
    cudaGetSymbolAddress((void**)&agg, g_agg);
    cudaGetSymbolAddress((void**)&nsrc, g_nsrc);
    cudaGetSymbolAddress((void**)&ndst, g_ndst);
    cudaGetSymbolAddress((void**)&dego, g_dego);
    cudaGetSymbolAddress((void**)&degi, g_degi);
    cudaGetSymbolAddress((void**)&off, g_off);
    cudaGetSymbolAddress((void**)&cur, g_cur);
    cudaGetSymbolAddress((void**)&csr, g_csr);
    cudaGetSymbolAddress((void**)&tsum, g_tsum);
    cudaGetSymbolAddress((void**)&wfrag, g_wfrag);

    const int MMA_SMEM128 = 128 * 136 * 2 + 4096 * 8;   // 67584
    const int MMA_SMEM64 = 128 * 72 * 2 + 2048 * 8;     // 34816
    cudaFuncSetAttribute((const void*)gemm_mma_kernel<8, false, true>,
                         cudaFuncAttributeMaxDynamicSharedMemorySize, MMA_SMEM128);
    cudaFuncSetAttribute((const void*)gemm_mma_kernel<8, false, false>,
                         cudaFuncAttributeMaxDynamicSharedMemorySize, MMA_SMEM128);
    cudaFuncSetAttribute((const void*)gemm_mma_kernel<4, true, true>,
                         cudaFuncAttributeMaxDynamicSharedMemorySize, MMA_SMEM64);

    // 0) weight fragment prep
    prep_wfrag_kernel<<<(3 * 4096 + 2048 + 255) / 256, 256>>>(Wp, Wl, wfrag);

    // 1) degrees -> norms + CSR(by dst)
    const int E4 = E >> 2;
    zero_deg_kernel<<<(N + 255) / 256, 256>>>(dego, degi, N);
    degree_kernel<<<(E4 + 255) / 256, 256>>>(src, dst, dego, degi, E);
    partsum_kernel<<<SCAN_T / 256, 256>>>(degi, tsum, N);
    scanpart_kernel<<<1, 1024>>>(tsum);
    writeoff_kernel<<<SCAN_T / 256, 256>>>(degi, dego, tsum, off, cur, nsrc, ndst, N);
    fill_kernel<<<(E4 + 255) / 256, 256>>>(src, dst, cur, csr, E);

    // 2) h = fp16( relu(x_raw @ Wp + bp) * norm_src )  — HMMA, K=64
    const int mma_blocks = (N + 127) / 128;
    gemm_mma_kernel<4, true, true><<<mma_blocks, 256, MMA_SMEM64>>>(
        x_raw, wfrag + 12288, bp, nsrc, h, N);

    // 3) layers: pull (fp16 agg) then HMMA GEMM (K=128)
    const int pull_blocks = (N * 32 + 255) / 256;
    for (int l = 0; l < 3; l++) {
        pull_kernel<<<pull_blocks, 256>>>(off, csr, ndst, (const uint2*)h, (uint2*)agg, N);
        const uint2* wf = wfrag + (long)l * 4096;
        const float* bcur = bl + (long)l * 128;
        if (l == 2) {
            gemm_mma_kernel<8, false, false><<<mma_blocks, 256, MMA_SMEM128>>>(
                (const void*)agg, wf, bcur, nullptr, out, N);
        } else {
            gemm_mma_kernel<8, false, true><<<mma_blocks, 256, MMA_SMEM128>>>(
                (const void*)agg, wf, bcur, nsrc, h, N);
        }
    }
}